// round 1
// baseline (speedup 1.0000x reference)
#include <cuda_runtime.h>
#include <cuda_bf16.h>

// Problem constants
#define L_DIM 256
#define C_DIM 20
#define B_DIM 1024
#define LC_DIM 5120   // L_DIM * C_DIM

// ---------------------------------------------------------------------------
// Kernel 1: out[b] = theta_0 + sum_i x[b,i] * theta_lc[i]
// One block per batch row, 256 threads, float4 loads, block reduce.
// ---------------------------------------------------------------------------
__global__ void init_out_kernel(const float* __restrict__ X,
                                const float* __restrict__ th0,
                                const float* __restrict__ thlc,
                                float* __restrict__ out) {
    int b = blockIdx.x;
    const float4* x4 = reinterpret_cast<const float4*>(X + (size_t)b * LC_DIM);
    const float4* t4 = reinterpret_cast<const float4*>(thlc);
    float s = 0.f;
    for (int i = threadIdx.x; i < LC_DIM / 4; i += blockDim.x) {
        float4 xv = x4[i];
        float4 tv = t4[i];
        s += xv.x * tv.x + xv.y * tv.y + xv.z * tv.z + xv.w * tv.w;
    }
    // warp reduce
    for (int o = 16; o > 0; o >>= 1) s += __shfl_xor_sync(0xffffffffu, s, o);
    __shared__ float red[8];
    int warp = threadIdx.x >> 5;
    if ((threadIdx.x & 31) == 0) red[warp] = s;
    __syncthreads();
    if (threadIdx.x == 0) {
        float t = 0.f;
        #pragma unroll
        for (int w = 0; w < 8; w++) t += red[w];
        out[b] = th0[0] + t;
    }
}

// ---------------------------------------------------------------------------
// Kernel 2: out[b] += x_b^T T x_b
// Tiled as a fused GEMM + dot:
//   Y[b, j] = sum_i X[b,i] * T[i,j]   (accumulated in registers per tile)
//   out[b] += sum_j Y[b,j] * X[b,j]
// Tile: BM=128 batches x BN=128 columns, BK=8 K-slice, 256 threads,
// 8x8 register micro-tile per thread (classic SGEMM layout).
// Triangle skip: T[i,j] nonzero requires i < floor(j/C)*C, so the K loop for
// a j-tile stops at Kmax = floor(j_max/C)*C (input theta_lclc is pre-masked,
// so any extra rows read inside the rounded-up K range are exact zeros).
// ---------------------------------------------------------------------------
#define BM 128
#define BN 128
#define BK 8
#define TM 8
#define TN 8

__global__ __launch_bounds__(256, 2)
void quad_kernel(const float* __restrict__ X,
                 const float* __restrict__ T,
                 float* __restrict__ out) {
    __shared__ float As[BK][BM + 4];   // +4 pad: conflict-free transposed stores
    __shared__ float Ts[BK][BN];

    const int tid = threadIdx.x;       // 0..255
    const int tx  = tid & 15;          // 0..15  -> j micro-tile
    const int ty  = tid >> 4;          // 0..15  -> b micro-tile
    const int j0  = blockIdx.x * BN;
    const int b0  = blockIdx.y * BM;

    // K bound from the mask structure (strictly upper in l-blocks of size C)
    const int Kmax   = ((j0 + BN - 1) / C_DIM) * C_DIM;    // exclusive
    const int Ksteps = (Kmax + BK - 1) / BK;               // <= 638 -> i < 5104 < LC

    // cooperative load indices
    const int arow = tid >> 1;          // 0..127 : batch row within tile
    const int acol = (tid & 1) * 4;     // 0 or 4 : k offset (float4)
    const int trow = tid >> 5;          // 0..7   : k row
    const int tcol = (tid & 31) * 4;    // 0..124 : j offset (float4)

    const float* Ap = X + (size_t)(b0 + arow) * LC_DIM + acol;
    const float* Tp = T + (size_t)trow * LC_DIM + j0 + tcol;

    float acc[TM][TN];
    #pragma unroll
    for (int m = 0; m < TM; m++)
        #pragma unroll
        for (int n = 0; n < TN; n++) acc[m][n] = 0.f;

    for (int ks = 0; ks < Ksteps; ks++) {
        float4 av = *reinterpret_cast<const float4*>(Ap + (size_t)ks * BK);
        float4 tv = *reinterpret_cast<const float4*>(Tp + (size_t)ks * BK * LC_DIM);
        As[acol + 0][arow] = av.x;
        As[acol + 1][arow] = av.y;
        As[acol + 2][arow] = av.z;
        As[acol + 3][arow] = av.w;
        *reinterpret_cast<float4*>(&Ts[trow][tcol]) = tv;
        __syncthreads();

        #pragma unroll
        for (int ik = 0; ik < BK; ik++) {
            float rm[TM], rn[TN];
            #pragma unroll
            for (int m = 0; m < TM; m++) rm[m] = As[ik][ty * TM + m];
            #pragma unroll
            for (int n = 0; n < TN; n++) rn[n] = Ts[ik][tx * TN + n];
            #pragma unroll
            for (int m = 0; m < TM; m++)
                #pragma unroll
                for (int n = 0; n < TN; n++)
                    acc[m][n] += rm[m] * rn[n];
        }
        __syncthreads();
    }

    // Epilogue: s[m] = sum_n acc[m][n] * X[b, j0 + tx*TN + n]
    float s[TM];
    #pragma unroll
    for (int m = 0; m < TM; m++) {
        const int b = b0 + ty * TM + m;
        const float* xr = X + (size_t)b * LC_DIM + j0 + tx * TN;
        float4 x0 = *reinterpret_cast<const float4*>(xr);
        float4 x1 = *reinterpret_cast<const float4*>(xr + 4);
        s[m] = acc[m][0] * x0.x + acc[m][1] * x0.y
             + acc[m][2] * x0.z + acc[m][3] * x0.w
             + acc[m][4] * x1.x + acc[m][5] * x1.y
             + acc[m][6] * x1.z + acc[m][7] * x1.w;
    }

    // Reduce across the 16 tx lanes (two 16-lane halves per warp), then
    // one atomicAdd per (b) from tx==0 lanes: 128 atomics per block.
    #pragma unroll
    for (int m = 0; m < TM; m++) {
        float v = s[m];
        v += __shfl_xor_sync(0xffffffffu, v, 8);
        v += __shfl_xor_sync(0xffffffffu, v, 4);
        v += __shfl_xor_sync(0xffffffffu, v, 2);
        v += __shfl_xor_sync(0xffffffffu, v, 1);
        if (tx == 0) atomicAdd(&out[b0 + ty * TM + m], v);
    }
}

// ---------------------------------------------------------------------------
// Launch. Inputs (metadata order):
//   d_in[0] x_lc       (B, L, C)        float32  -> (B, LC)
//   d_in[1] theta_0    (1,)             float32
//   d_in[2] theta_lc   (1, L, C)        float32  -> (LC)
//   d_in[3] theta_lclc (1, L, C, L, C)  float32  -> (LC, LC), already masked
//   d_in[4] mask       (L, L)           unused (theta_lclc is pre-masked)
// Output: (B, 1) float32
// ---------------------------------------------------------------------------
extern "C" void kernel_launch(void* const* d_in, const int* in_sizes, int n_in,
                              void* d_out, int out_size) {
    const float* x      = (const float*)d_in[0];
    const float* th0    = (const float*)d_in[1];
    const float* thlc   = (const float*)d_in[2];
    const float* thlclc = (const float*)d_in[3];
    float* out = (float*)d_out;

    init_out_kernel<<<B_DIM, 256>>>(x, th0, thlc, out);

    dim3 grid(LC_DIM / BN, B_DIM / BM);   // (40, 8)
    quad_kernel<<<grid, 256>>>(x, thlclc, out);
}

// round 2
// speedup vs baseline: 2.2979x; 2.2979x over previous
#include <cuda_runtime.h>
#include <cuda_bf16.h>
#include <cstdint>

#define L_DIM 256
#define C_DIM 20
#define B_DIM 1024
#define LC_DIM 5120

// ---------------------------------------------------------------------------
// Kernel 1: out[b] = theta_0 + sum_i x[b,i] * theta_lc[i]
// ---------------------------------------------------------------------------
__global__ void init_out_kernel(const float* __restrict__ X,
                                const float* __restrict__ th0,
                                const float* __restrict__ thlc,
                                float* __restrict__ out) {
    int b = blockIdx.x;
    const float4* x4 = reinterpret_cast<const float4*>(X + (size_t)b * LC_DIM);
    const float4* t4 = reinterpret_cast<const float4*>(thlc);
    float s = 0.f;
    for (int i = threadIdx.x; i < LC_DIM / 4; i += blockDim.x) {
        float4 xv = x4[i];
        float4 tv = t4[i];
        s += xv.x * tv.x + xv.y * tv.y + xv.z * tv.z + xv.w * tv.w;
    }
    for (int o = 16; o > 0; o >>= 1) s += __shfl_xor_sync(0xffffffffu, s, o);
    __shared__ float red[8];
    int warp = threadIdx.x >> 5;
    if ((threadIdx.x & 31) == 0) red[warp] = s;
    __syncthreads();
    if (threadIdx.x == 0) {
        float t = 0.f;
        #pragma unroll
        for (int w = 0; w < 8; w++) t += red[w];
        out[b] = th0[0] + t;
    }
}

// ---------------------------------------------------------------------------
// Kernel 2 (tensor cores, tf32): out[b] += x_b^T T x_b
//
// GEMM C[b,j] = sum_i X[b,i] T[i,j], fused with dot against X[b,j].
// CTA tile 128(b) x 128(j) x BK=32, 128 threads = 4 warps (2x2 of 64x64).
// mma.sync.aligned.m16n8k8 tf32, fp32 accumulate.
//
// Shared layouts (both 128 rows x 36 words, k-permuted):
//   As[row][k']  row = batch-row,  k' = (k%4)*8 + k/4
//   Bs[n  ][k']  n   = T column,   same permutation (B fragment is k x n
//                                  col-major, so n plays the "row" role)
// With this permutation a thread's fragment elements for 2 k-slices are ONE
// float4 at [row][8q + 4h], q = lane%4. Stride 36 words makes both the
// STS32 staging pattern and the LDS128 fragment pattern bank-conflict-free
// (verified: stores hit banks 4g+q (0..31 distinct); 128-bit loads hit
// 16B-superbanks (g+2q+h)%8 distinct per quarter-warp phase).
// Triangle skip: T[i,j]=0 unless i/C < j/C, so K stops at
// Kmax = floor((j0+127)/C)*C; padding rows inside the rounded BK are exact
// zeros in theta_lclc (it is pre-masked by setup).
// ---------------------------------------------------------------------------
#define BN 128
#define BM 128
#define BKQ 32

__device__ __forceinline__ uint32_t f2tf32(float f) {
    uint32_t u;
    asm("cvt.rna.tf32.f32 %0, %1;" : "=r"(u) : "f"(f));
    return u;
}

__device__ __forceinline__ void mma_tf32(float c[4],
                                         uint32_t a0, uint32_t a1,
                                         uint32_t a2, uint32_t a3,
                                         uint32_t b0, uint32_t b1) {
    asm("mma.sync.aligned.m16n8k8.row.col.f32.tf32.tf32.f32 "
        "{%0,%1,%2,%3}, {%4,%5,%6,%7}, {%8,%9}, {%0,%1,%2,%3};"
        : "+f"(c[0]), "+f"(c[1]), "+f"(c[2]), "+f"(c[3])
        : "r"(a0), "r"(a1), "r"(a2), "r"(a3), "r"(b0), "r"(b1));
}

__global__ __launch_bounds__(128, 2)
void quad_tc_kernel(const float* __restrict__ X,
                    const float* __restrict__ T,
                    float* __restrict__ out) {
    __shared__ uint32_t As[128][36];
    __shared__ uint32_t Bs[128][36];

    const int tid  = threadIdx.x;
    const int lane = tid & 31;
    const int w    = tid >> 5;       // warp 0..3
    const int g    = lane >> 2;      // 0..7  (groupID)
    const int q    = lane & 3;       // 0..3  (thread-in-group)
    const int wm   = w & 1;          // warp_m: 0..1  (64 rows each)
    const int wn   = w >> 1;         // warp_n: 0..1  (64 cols each)

    // heaviest j-tiles first (work ~ j0 due to triangle skip)
    const int jt = gridDim.x - 1 - blockIdx.x;
    const int j0 = jt * BN;
    const int b0 = blockIdx.y * BM;

    const int Kmax   = ((j0 + BN - 1) / C_DIM) * C_DIM;  // exclusive
    const int Ksteps = (Kmax + BKQ - 1) / BKQ;           // Ksteps*32 <= 5120

    float acc[4][8][4];
    #pragma unroll
    for (int mt = 0; mt < 4; mt++)
        #pragma unroll
        for (int nt = 0; nt < 8; nt++)
            #pragma unroll
            for (int c = 0; c < 4; c++) acc[mt][nt][c] = 0.f;

    const int kp_b = q * 8 + g;  // k' for B staging (k = lane)

    for (int ks = 0; ks < Ksteps; ks++) {
        const int k0 = ks * BKQ;
        __syncthreads();

        // ---- stage A: X[b0..b0+127][k0..k0+31] -> As (tf32, k-permuted)
        #pragma unroll
        for (int m = 0; m < 4; m++) {
            const int row = w * 32 + g + 8 * m;
            const float* src = X + (size_t)(b0 + row) * LC_DIM + k0;
            #pragma unroll
            for (int cc = 0; cc < 2; cc++) {
                const int c = q + 4 * cc;                 // 4-elem chunk id
                float4 v = *reinterpret_cast<const float4*>(src + 4 * c);
                As[row][c]      = f2tf32(v.x);   // k=4c+0 -> k'=0*8+c
                As[row][8 + c]  = f2tf32(v.y);   // k=4c+1
                As[row][16 + c] = f2tf32(v.z);   // k=4c+2
                As[row][24 + c] = f2tf32(v.w);   // k=4c+3
            }
        }
        // ---- stage B: T[k0+lane][j0 + n] -> Bs[n][k'] (transpose via STS32)
        {
            const float* srcT = T + (size_t)(k0 + lane) * LC_DIM + j0;
            #pragma unroll
            for (int s = 0; s < 4; s++) {
                const int n0 = w * 32 + 8 * s;
                float4 v0 = *reinterpret_cast<const float4*>(srcT + n0);
                float4 v1 = *reinterpret_cast<const float4*>(srcT + n0 + 4);
                Bs[n0 + 0][kp_b] = f2tf32(v0.x);
                Bs[n0 + 1][kp_b] = f2tf32(v0.y);
                Bs[n0 + 2][kp_b] = f2tf32(v0.z);
                Bs[n0 + 3][kp_b] = f2tf32(v0.w);
                Bs[n0 + 4][kp_b] = f2tf32(v1.x);
                Bs[n0 + 5][kp_b] = f2tf32(v1.y);
                Bs[n0 + 6][kp_b] = f2tf32(v1.z);
                Bs[n0 + 7][kp_b] = f2tf32(v1.w);
            }
        }
        __syncthreads();

        // ---- compute: 2 halves x 2 k-slices = 4 k-slices of 8
        #pragma unroll
        for (int h = 0; h < 2; h++) {
            uint4 afl[4], afh[4];
            #pragma unroll
            for (int mt = 0; mt < 4; mt++) {
                const int r = wm * 64 + mt * 16 + g;
                afl[mt] = *reinterpret_cast<const uint4*>(&As[r][q * 8 + 4 * h]);
                afh[mt] = *reinterpret_cast<const uint4*>(&As[r + 8][q * 8 + 4 * h]);
            }
            uint4 bf[8];
            #pragma unroll
            for (int nt = 0; nt < 8; nt++) {
                const int n = wn * 64 + nt * 8 + g;
                bf[nt] = *reinterpret_cast<const uint4*>(&Bs[n][q * 8 + 4 * h]);
            }
            // element e of the float4: e=0 -> (slice 2h+0, a0/b0),
            // e=1 -> (2h+0, a2/b1), e=2 -> (2h+1, a0/b0), e=3 -> (2h+1, a2/b1)
            #pragma unroll
            for (int t = 0; t < 2; t++) {
                #pragma unroll
                for (int mt = 0; mt < 4; mt++) {
                    const uint32_t a0 = (t == 0) ? afl[mt].x : afl[mt].z;
                    const uint32_t a2 = (t == 0) ? afl[mt].y : afl[mt].w;
                    const uint32_t a1 = (t == 0) ? afh[mt].x : afh[mt].z;
                    const uint32_t a3 = (t == 0) ? afh[mt].y : afh[mt].w;
                    #pragma unroll
                    for (int nt = 0; nt < 8; nt++) {
                        const uint32_t b0r = (t == 0) ? bf[nt].x : bf[nt].z;
                        const uint32_t b1r = (t == 0) ? bf[nt].y : bf[nt].w;
                        mma_tf32(acc[mt][nt], a0, a1, a2, a3, b0r, b1r);
                    }
                }
            }
        }
    }

    // ---- fused epilogue: out[b] += sum_j C[b,j] * X[b,j]
    // c0: (row g,   col 2q), c1: (g, 2q+1), c2: (g+8, 2q), c3: (g+8, 2q+1)
    #pragma unroll
    for (int mt = 0; mt < 4; mt++) {
        #pragma unroll
        for (int hh = 0; hh < 2; hh++) {
            const int b = b0 + wm * 64 + mt * 16 + g + 8 * hh;
            const float* xr = X + (size_t)b * LC_DIM + j0 + wn * 64;
            float s = 0.f;
            #pragma unroll
            for (int nt = 0; nt < 8; nt++) {
                float2 xv = *reinterpret_cast<const float2*>(xr + nt * 8 + 2 * q);
                s += acc[mt][nt][2 * hh] * xv.x + acc[mt][nt][2 * hh + 1] * xv.y;
            }
            s += __shfl_xor_sync(0xffffffffu, s, 1);
            s += __shfl_xor_sync(0xffffffffu, s, 2);
            if (q == 0) atomicAdd(&out[b], s);
        }
    }
}

// ---------------------------------------------------------------------------
// Inputs: x_lc (B,L,C) f32 | theta_0 (1,) | theta_lc (1,L,C) |
//         theta_lclc (1,L,C,L,C) pre-masked | mask (unused)
// Output: (B,1) f32
// ---------------------------------------------------------------------------
extern "C" void kernel_launch(void* const* d_in, const int* in_sizes, int n_in,
                              void* d_out, int out_size) {
    const float* x      = (const float*)d_in[0];
    const float* th0    = (const float*)d_in[1];
    const float* thlc   = (const float*)d_in[2];
    const float* thlclc = (const float*)d_in[3];
    float* out = (float*)d_out;

    init_out_kernel<<<B_DIM, 256>>>(x, th0, thlc, out);

    dim3 grid(LC_DIM / BN, B_DIM / BM);   // (40, 8)
    quad_tc_kernel<<<grid, 128>>>(x, thlclc, out);
}

// round 4
// speedup vs baseline: 2.4394x; 1.0616x over previous
#include <cuda_runtime.h>
#include <cstdint>

#define B_DIM 1024
#define C_DIM 20
#define LC    5120
#define KC    160          // LC / 32 K-chunks

// ---------------------------------------------------------------------------
// Scratch (static __device__, allocation-free):
//   g_Xp[b][kc][k']  tf32 bits of X, k-permuted within each 32-chunk
//   g_Tp[j][kc][k']  tf32 bits of T^T (K-major), same permutation
// permutation: k' = (k%4)*8 + k/4  (k local to the 32-chunk)
// -> the R2-verified conflict-free LDS128 fragment pattern applies unchanged.
// ---------------------------------------------------------------------------
__device__ uint32_t g_Xp[(size_t)B_DIM * LC];
__device__ uint32_t g_Tp[(size_t)LC * LC];

__device__ __forceinline__ uint32_t f2tf32(float f) {
    uint32_t u;
    asm("cvt.rna.tf32.f32 %0, %1;" : "=r"(u) : "f"(f));
    return u;
}
__device__ __forceinline__ uint32_t smem_u32(const void* p) {
    uint32_t a;
    asm("{ .reg .u64 t; cvta.to.shared.u64 t, %1; cvt.u32.u64 %0, t; }"
        : "=r"(a) : "l"(p));
    return a;
}
__device__ __forceinline__ void cpa16(uint32_t dst, const uint32_t* src) {
    asm volatile("cp.async.cg.shared.global [%0], [%1], 16;"
                 :: "r"(dst), "l"(__cvta_generic_to_global(src)));
}
#define CP_COMMIT() asm volatile("cp.async.commit_group;" ::: "memory")
#define CP_WAIT2()  asm volatile("cp.async.wait_group 2;" ::: "memory")

__device__ __forceinline__ void mma_tf32(float c[4],
                                         uint32_t a0, uint32_t a1,
                                         uint32_t a2, uint32_t a3,
                                         uint32_t b0, uint32_t b1) {
    asm("mma.sync.aligned.m16n8k8.row.col.f32.tf32.tf32.f32 "
        "{%0,%1,%2,%3}, {%4,%5,%6,%7}, {%8,%9}, {%0,%1,%2,%3};"
        : "+f"(c[0]), "+f"(c[1]), "+f"(c[2]), "+f"(c[3])
        : "r"(a0), "r"(a1), "r"(a2), "r"(a3), "r"(b0), "r"(b1));
}

// ---------------------------------------------------------------------------
// prep_X: X -> tf32 bits, permuted chunks. 1024 blocks x 256.
// ---------------------------------------------------------------------------
__global__ void prep_X(const float* __restrict__ X) {
    const int b = blockIdx.x;
    for (int k = threadIdx.x; k < LC; k += blockDim.x) {
        uint32_t t = f2tf32(X[(size_t)b * LC + k]);
        const int kc = k >> 5, kl = k & 31;
        const int kp = (kl & 3) * 8 + (kl >> 2);
        g_Xp[((size_t)b * KC + kc) * 32 + kp] = t;
    }
}

// prep_T: transpose T (pre-masked) -> K-major tf32 bits, permuted chunks.
// Block (32,32), grid (KC, KC). Coalesced read and write.
__global__ void prep_T(const float* __restrict__ T) {
    __shared__ float tile[32][33];
    const int i0 = blockIdx.x * 32;          // k tile
    const int j0 = blockIdx.y * 32;          // j tile
    const int tx = threadIdx.x, ty = threadIdx.y;
    tile[ty][tx] = T[(size_t)(i0 + ty) * LC + j0 + tx];
    __syncthreads();
    const float v = tile[tx][ty];            // T[i0+tx][j0+ty]
    const int kp = (tx & 3) * 8 + (tx >> 2);
    g_Tp[((size_t)(j0 + ty) * KC + (i0 >> 5)) * 32 + kp] = f2tf32(v);
}

// ---------------------------------------------------------------------------
// out[b] = theta_0 + <theta_lc, x_b>
// ---------------------------------------------------------------------------
__global__ void init_out_kernel(const float* __restrict__ X,
                                const float* __restrict__ th0,
                                const float* __restrict__ thlc,
                                float* __restrict__ out) {
    int b = blockIdx.x;
    const float4* x4 = reinterpret_cast<const float4*>(X + (size_t)b * LC);
    const float4* t4 = reinterpret_cast<const float4*>(thlc);
    float s = 0.f;
    for (int i = threadIdx.x; i < LC / 4; i += blockDim.x) {
        float4 xv = x4[i], tv = t4[i];
        s += xv.x * tv.x + xv.y * tv.y + xv.z * tv.z + xv.w * tv.w;
    }
    for (int o = 16; o > 0; o >>= 1) s += __shfl_xor_sync(0xffffffffu, s, o);
    __shared__ float red[8];
    if ((threadIdx.x & 31) == 0) red[threadIdx.x >> 5] = s;
    __syncthreads();
    if (threadIdx.x == 0) {
        float t = 0.f;
        #pragma unroll
        for (int w = 0; w < 8; w++) t += red[w];
        out[b] = th0[0] + t;
    }
}

// ---------------------------------------------------------------------------
// quad kernel: out[b] += x_b^T T x_b
// CTA 128(b) x 128(j) x BK=32, 256 threads (8 warps, 2m x 4n of 64x32),
// 3-stage cp.async pipeline, fused dot epilogue.
// Smem row stride 36 words (144B): conflict-free STS(LDGSTS) + LDS128.
// Triangle skip: K to Kmax = floor((j0+127)/C)*C rounded up to 32
// (pre-masked zeros in T make padding exact).
// ---------------------------------------------------------------------------
#define STAGE_BYTES 36864          // (A 128x36 + B 128x36) words
#define BOFF        18432
#define SMEM_TOTAL  (3 * STAGE_BYTES)

__device__ __forceinline__ void stage_load(uint32_t sb, int ss, int kc,
                                           int b0, int j0, int tid) {
    const uint32_t st = sb + ss * STAGE_BYTES;
    #pragma unroll
    for (int i = 0; i < 4; i++) {
        const int idx = tid + i * 256;        // 0..1023
        const int row = idx >> 3, c = idx & 7;
        cpa16(st + row * 144 + c * 16,
              g_Xp + ((size_t)(b0 + row) * KC + kc) * 32 + c * 4);
    }
    #pragma unroll
    for (int i = 0; i < 4; i++) {
        const int idx = tid + i * 256;
        const int row = idx >> 3, c = idx & 7;
        cpa16(st + BOFF + row * 144 + c * 16,
              g_Tp + ((size_t)(j0 + row) * KC + kc) * 32 + c * 4);
    }
}

__global__ __launch_bounds__(256, 2)
void quad_tc_kernel(const float* __restrict__ X, float* __restrict__ out) {
    extern __shared__ char smem[];
    const uint32_t sb = smem_u32(smem);
    const int tid  = threadIdx.x;
    const int lane = tid & 31;
    const int w    = tid >> 5;
    const int g    = lane >> 2;
    const int q    = lane & 3;
    const int wm   = w & 1;       // 0..1 : 64 batch rows
    const int wn   = w >> 1;      // 0..3 : 32 j cols

    // work-balanced tile map: ranks sorted heavy->light; pairs (bid,bid+148)
    // sum to ~const; wave-2 bids (296..319) get the 24 lightest tiles.
    const int bid = blockIdx.x;
    int r;
    if (bid < 148)      r = bid * 2;              // even ranks 0..294
    else if (bid < 296) r = 591 - 2 * bid;        // odd ranks 295..1
    else                r = bid;                  // 296..319 (lightest)
    const int jt = 39 - (r >> 3);
    const int b0 = (r & 7) << 7;
    const int j0 = jt << 7;

    const int Kmax = ((j0 + 127) / C_DIM) * C_DIM;
    const int KPP  = (Kmax + 31) >> 5;            // 4..160 K-chunks

    float acc[4][4][4];
    #pragma unroll
    for (int mt = 0; mt < 4; mt++)
        #pragma unroll
        for (int nt = 0; nt < 4; nt++)
            #pragma unroll
            for (int c = 0; c < 4; c++) acc[mt][nt][c] = 0.f;

    // prologue: preload 3 stages (KPP >= 4 always)
    #pragma unroll
    for (int s = 0; s < 3; s++) { stage_load(sb, s, s, b0, j0, tid); CP_COMMIT(); }

    for (int ks = 0; ks < KPP; ks++) {
        const int ss = ks % 3;
        CP_WAIT2();
        __syncthreads();

        const uint32_t aB = sb + ss * STAGE_BYTES;
        const uint32_t bB = aB + BOFF;

        #pragma unroll
        for (int h = 0; h < 2; h++) {
            uint4 bf[4];
            #pragma unroll
            for (int nt = 0; nt < 4; nt++) {
                const uint32_t off = bB + (wn * 32 + nt * 8 + g) * 144
                                        + (q * 8 + 4 * h) * 4;
                bf[nt] = *reinterpret_cast<const uint4*>(smem + (off - sb));
            }
            #pragma unroll
            for (int mt = 0; mt < 4; mt++) {
                const uint32_t offl = aB + (wm * 64 + mt * 16 + g) * 144
                                         + (q * 8 + 4 * h) * 4;
                uint4 afl = *reinterpret_cast<const uint4*>(smem + (offl - sb));
                uint4 afh = *reinterpret_cast<const uint4*>(smem + (offl - sb) + 8 * 144);
                #pragma unroll
                for (int t = 0; t < 2; t++) {
                    const uint32_t a0 = t ? afl.z : afl.x;
                    const uint32_t a2 = t ? afl.w : afl.y;
                    const uint32_t a1 = t ? afh.z : afh.x;
                    const uint32_t a3 = t ? afh.w : afh.y;
                    #pragma unroll
                    for (int nt = 0; nt < 4; nt++) {
                        const uint32_t b0r = t ? bf[nt].z : bf[nt].x;
                        const uint32_t b1r = t ? bf[nt].w : bf[nt].y;
                        mma_tf32(acc[mt][nt], a0, a1, a2, a3, b0r, b1r);
                    }
                }
            }
        }
        __syncthreads();
        if (ks + 3 < KPP) stage_load(sb, ss, ks + 3, b0, j0, tid);
        CP_COMMIT();   // always commit to keep group count in lockstep
    }

    // fused epilogue: out[b] += sum_j C[b,j] * X[b,j]
    // c0:(g,2q) c1:(g,2q+1) c2:(g+8,2q) c3:(g+8,2q+1) within each 16x8 tile
    #pragma unroll
    for (int mt = 0; mt < 4; mt++) {
        #pragma unroll
        for (int hh = 0; hh < 2; hh++) {
            const int b = b0 + wm * 64 + mt * 16 + g + 8 * hh;
            const float* xr = X + (size_t)b * LC + j0 + wn * 32;
            float s = 0.f;
            #pragma unroll
            for (int nt = 0; nt < 4; nt++) {
                float2 xv = *reinterpret_cast<const float2*>(xr + nt * 8 + 2 * q);
                s += acc[mt][nt][2 * hh] * xv.x + acc[mt][nt][2 * hh + 1] * xv.y;
            }
            s += __shfl_xor_sync(0xffffffffu, s, 1);
            s += __shfl_xor_sync(0xffffffffu, s, 2);
            if (q == 0) atomicAdd(&out[b], s);
        }
    }
}

// ---------------------------------------------------------------------------
// Inputs: x_lc (B,L,C) f32 | theta_0 (1,) | theta_lc (1,L,C) |
//         theta_lclc (1,L,C,L,C) pre-masked f32 | mask (unused)
// Output: (B,1) f32
// ---------------------------------------------------------------------------
extern "C" void kernel_launch(void* const* d_in, const int* in_sizes, int n_in,
                              void* d_out, int out_size) {
    const float* x      = (const float*)d_in[0];
    const float* th0    = (const float*)d_in[1];
    const float* thlc   = (const float*)d_in[2];
    const float* thlclc = (const float*)d_in[3];
    float* out = (float*)d_out;

    cudaFuncSetAttribute(quad_tc_kernel,
                         cudaFuncAttributeMaxDynamicSharedMemorySize, SMEM_TOTAL);

    prep_X<<<B_DIM, 256>>>(x);
    prep_T<<<dim3(KC, KC), dim3(32, 32)>>>(thlclc);
    init_out_kernel<<<B_DIM, 256>>>(x, th0, thlc, out);

    quad_tc_kernel<<<320, 256, SMEM_TOTAL>>>(x, out);
}

// round 5
// speedup vs baseline: 3.3149x; 1.3589x over previous
#include <cuda_runtime.h>
#include <cstdint>

#define B_DIM 1024
#define C_DIM 20
#define LC    5120
#define KC    160          // LC / 32 K-chunks

// ---------------------------------------------------------------------------
// Scratch: tf32 bit patterns, K-major, k-permuted within each 32-chunk.
//   g_Xp[b][kc][k']   g_Tp[j][kc][k']   k' = (k%4)*8 + k/4
// ---------------------------------------------------------------------------
__device__ uint32_t g_Xp[(size_t)B_DIM * LC];
__device__ uint32_t g_Tp[(size_t)LC * LC];

__device__ __forceinline__ uint32_t f2tf32(float f) {
    uint32_t u;
    asm("cvt.rna.tf32.f32 %0, %1;" : "=r"(u) : "f"(f));
    return u;
}
__device__ __forceinline__ uint32_t smem_u32(const void* p) {
    uint32_t a;
    asm("{ .reg .u64 t; cvta.to.shared.u64 t, %1; cvt.u32.u64 %0, t; }"
        : "=r"(a) : "l"(p));
    return a;
}
__device__ __forceinline__ void cpa16(uint32_t dst, const char* gbase, uint32_t goff) {
    asm volatile("cp.async.cg.shared.global [%0], [%1], 16;"
                 :: "r"(dst), "l"(__cvta_generic_to_global(gbase + goff)));
}
#define CP_COMMIT() asm volatile("cp.async.commit_group;" ::: "memory")
#define CP_WAIT1()  asm volatile("cp.async.wait_group 1;" ::: "memory")

__device__ __forceinline__ void mma_tf32(float c[4],
                                         uint32_t a0, uint32_t a1,
                                         uint32_t a2, uint32_t a3,
                                         uint32_t b0, uint32_t b1) {
    asm("mma.sync.aligned.m16n8k8.row.col.f32.tf32.tf32.f32 "
        "{%0,%1,%2,%3}, {%4,%5,%6,%7}, {%8,%9}, {%0,%1,%2,%3};"
        : "+f"(c[0]), "+f"(c[1]), "+f"(c[2]), "+f"(c[3])
        : "r"(a0), "r"(a1), "r"(a2), "r"(a3), "r"(b0), "r"(b1));
}

// ---------------------------------------------------------------------------
// prep_X: X -> tf32 bits (permuted chunks) AND out[b] = th0 + <thlc, x_b>
// ---------------------------------------------------------------------------
__global__ void prep_X(const float* __restrict__ X,
                       const float* __restrict__ th0,
                       const float* __restrict__ thlc,
                       float* __restrict__ out) {
    const int b = blockIdx.x;
    const float* xr = X + (size_t)b * LC;
    float s = 0.f;
    for (int k4 = threadIdx.x; k4 < LC / 4; k4 += blockDim.x) {
        const float4 xv = *reinterpret_cast<const float4*>(xr + k4 * 4);
        const float4 tv = *reinterpret_cast<const float4*>(thlc + k4 * 4);
        s += xv.x * tv.x + xv.y * tv.y + xv.z * tv.z + xv.w * tv.w;
        const int k = k4 * 4;            // k..k+3 share (k%4 cycle)
        const int kc = k >> 5;
        const int kl = k & 31;           // multiple of 4 -> kl/4 = chunkpos
        uint32_t* dst = g_Xp + ((size_t)b * KC + kc) * 32 + (kl >> 2);
        dst[0]  = f2tf32(xv.x);          // k%4==0 -> k' = 0*8 + kl/4
        dst[8]  = f2tf32(xv.y);
        dst[16] = f2tf32(xv.z);
        dst[24] = f2tf32(xv.w);
    }
    for (int o = 16; o > 0; o >>= 1) s += __shfl_xor_sync(0xffffffffu, s, o);
    __shared__ float red[8];
    if ((threadIdx.x & 31) == 0) red[threadIdx.x >> 5] = s;
    __syncthreads();
    if (threadIdx.x == 0) {
        float t = 0.f;
        #pragma unroll
        for (int w = 0; w < 8; w++) t += red[w];
        out[b] = th0[0] + t;
    }
}

// prep_T: transpose T (pre-masked) -> K-major tf32 bits, permuted chunks.
__global__ void prep_T(const float* __restrict__ T) {
    __shared__ float tile[32][33];
    const int i0 = blockIdx.x * 32;          // k tile
    const int j0 = blockIdx.y * 32;          // j tile
    const int tx = threadIdx.x, ty = threadIdx.y;
    tile[ty][tx] = T[(size_t)(i0 + ty) * LC + j0 + tx];
    __syncthreads();
    const float v = tile[tx][ty];            // T[i0+tx][j0+ty]
    const int kp = (tx & 3) * 8 + (tx >> 2);
    g_Tp[((size_t)(j0 + ty) * KC + (i0 >> 5)) * 32 + kp] = f2tf32(v);
}

// ---------------------------------------------------------------------------
// quad kernel: out[b] += x_b^T T x_b
// CTA 128(b) x 128(j) x BK=32, 256 threads (8 warps: 2m x 4n of 64x32),
// 3-stage cp.async pipeline with prefetch distance 2 and ONE barrier/chunk.
// Smem rows 36 words (144B): conflict-free STS + LDS128 (R2-verified layout).
// Triangle skip: K to Kmax = floor((j0+127)/C)*C rounded up to 32.
// ---------------------------------------------------------------------------
#define STAGE_BYTES 36864
#define BOFF        18432
#define SMEM_TOTAL  (3 * STAGE_BYTES)

__global__ __launch_bounds__(256, 2)
void quad_tc_kernel(const float* __restrict__ X, float* __restrict__ out) {
    extern __shared__ char smem[];
    const uint32_t sb = smem_u32(smem);
    const int tid  = threadIdx.x;
    const int lane = tid & 31;
    const int w    = tid >> 5;
    const int g    = lane >> 2;
    const int q    = lane & 3;
    const int wm   = w & 1;       // 0..1 : 64 batch rows
    const int wn   = w >> 1;      // 0..3 : 32 j cols

    // work-balanced tile map (heavy->light; co-resident pairs sum ~const)
    const int bid = blockIdx.x;
    int r;
    if (bid < 148)      r = bid * 2;
    else if (bid < 296) r = 591 - 2 * bid;
    else                r = bid;
    const int jt = 39 - (r >> 3);
    const int b0 = (r & 7) << 7;
    const int j0 = jt << 7;

    const int Kmax = ((j0 + 127) / C_DIM) * C_DIM;
    const int KPP  = (Kmax + 31) >> 5;            // 4..160 K-chunks

    // ---- hoisted cp.async source offsets (bytes) and smem dst offsets ----
    const int rowL = tid >> 3;                    // 0..31 within each i-block
    const int ch   = tid & 7;                     // 16B chunk 0..7
    // global byte offsets, constant part (row stride KC*128 B)
    uint32_t gAc[4], gBc[4];
    #pragma unroll
    for (int i = 0; i < 4; i++) {
        const int row = rowL + i * 32;
        gAc[i] = (uint32_t)((b0 + row) * (KC * 128) + ch * 16);
        gBc[i] = (uint32_t)((j0 + row) * (KC * 128) + ch * 16);
    }
    const uint32_t sAc = (uint32_t)(rowL * 144 + ch * 16); // + i*32*144
    const char* gA = (const char*)g_Xp;
    const char* gB = (const char*)g_Tp;

    float acc[4][4][4];
    #pragma unroll
    for (int mt = 0; mt < 4; mt++)
        #pragma unroll
        for (int nt = 0; nt < 4; nt++)
            #pragma unroll
            for (int c = 0; c < 4; c++) acc[mt][nt][c] = 0.f;

    // ---- prologue: prefetch chunks 0,1 into stages 0,1 (KPP >= 4) ----
    #pragma unroll
    for (int s = 0; s < 2; s++) {
        const uint32_t st = sb + s * STAGE_BYTES + sAc;
        const uint32_t ko = (uint32_t)s * 128;
        #pragma unroll
        for (int i = 0; i < 4; i++) cpa16(st + i * (32 * 144), gA, gAc[i] + ko);
        #pragma unroll
        for (int i = 0; i < 4; i++) cpa16(st + BOFF + i * (32 * 144), gB, gBc[i] + ko);
        CP_COMMIT();
    }

    // per-warp fragment smem offsets (constant)
    const uint32_t fA = (uint32_t)((wm * 64 + g) * 144 + q * 32);
    const uint32_t fB = (uint32_t)(BOFF + (wn * 32 + g) * 144 + q * 32);

    int ss = 0;
    for (int ks = 0; ks < KPP; ks++) {
        CP_WAIT1();
        __syncthreads();

        const char* aB = smem + ss * STAGE_BYTES;

        #pragma unroll
        for (int h = 0; h < 2; h++) {
            uint4 bf[4];
            #pragma unroll
            for (int nt = 0; nt < 4; nt++)
                bf[nt] = *reinterpret_cast<const uint4*>(aB + fB + nt * (8 * 144) + h * 16);
            #pragma unroll
            for (int mt = 0; mt < 4; mt++) {
                const char* ap = aB + fA + mt * (16 * 144) + h * 16;
                uint4 afl = *reinterpret_cast<const uint4*>(ap);
                uint4 afh = *reinterpret_cast<const uint4*>(ap + 8 * 144);
                #pragma unroll
                for (int t = 0; t < 2; t++) {
                    const uint32_t a0 = t ? afl.z : afl.x;
                    const uint32_t a2 = t ? afl.w : afl.y;
                    const uint32_t a1 = t ? afh.z : afh.x;
                    const uint32_t a3 = t ? afh.w : afh.y;
                    #pragma unroll
                    for (int nt = 0; nt < 4; nt++) {
                        const uint32_t b0r = t ? bf[nt].z : bf[nt].x;
                        const uint32_t b1r = t ? bf[nt].w : bf[nt].y;
                        mma_tf32(acc[mt][nt], a0, a1, a2, a3, b0r, b1r);
                    }
                }
            }
        }

        // prefetch chunk ks+2 into stage (ss+2)%3 — disjoint from any stage
        // readable by laggard warps (they can only be reading ss or issuing
        // into (ss+1)%3 from the previous iteration).
        if (ks + 2 < KPP) {
            const int s2 = (ss + 2 >= 3) ? ss - 1 : ss + 2;
            const uint32_t st = sb + s2 * STAGE_BYTES + sAc;
            const uint32_t ko = (uint32_t)(ks + 2) * 128;
            #pragma unroll
            for (int i = 0; i < 4; i++) cpa16(st + i * (32 * 144), gA, gAc[i] + ko);
            #pragma unroll
            for (int i = 0; i < 4; i++) cpa16(st + BOFF + i * (32 * 144), gB, gBc[i] + ko);
        }
        CP_COMMIT();   // all threads commit every iteration (group lockstep)

        ss = (ss + 1 >= 3) ? 0 : ss + 1;
    }

    // ---- fused epilogue: out[b] += sum_j C[b,j] * X[b,j] ----
    #pragma unroll
    for (int mt = 0; mt < 4; mt++) {
        #pragma unroll
        for (int hh = 0; hh < 2; hh++) {
            const int b = b0 + wm * 64 + mt * 16 + g + 8 * hh;
            const float* xr = X + (size_t)b * LC + j0 + wn * 32;
            float s = 0.f;
            #pragma unroll
            for (int nt = 0; nt < 4; nt++) {
                float2 xv = *reinterpret_cast<const float2*>(xr + nt * 8 + 2 * q);
                s += acc[mt][nt][2 * hh] * xv.x + acc[mt][nt][2 * hh + 1] * xv.y;
            }
            s += __shfl_xor_sync(0xffffffffu, s, 1);
            s += __shfl_xor_sync(0xffffffffu, s, 2);
            if (q == 0) atomicAdd(&out[b], s);
        }
    }
}

// ---------------------------------------------------------------------------
// Inputs: x_lc (B,L,C) f32 | theta_0 (1,) | theta_lc (1,L,C) |
//         theta_lclc (1,L,C,L,C) pre-masked f32 | mask (unused)
// Output: (B,1) f32
// ---------------------------------------------------------------------------
extern "C" void kernel_launch(void* const* d_in, const int* in_sizes, int n_in,
                              void* d_out, int out_size) {
    const float* x      = (const float*)d_in[0];
    const float* th0    = (const float*)d_in[1];
    const float* thlc   = (const float*)d_in[2];
    const float* thlclc = (const float*)d_in[3];
    float* out = (float*)d_out;

    cudaFuncSetAttribute(quad_tc_kernel,
                         cudaFuncAttributeMaxDynamicSharedMemorySize, SMEM_TOTAL);

    prep_X<<<B_DIM, 256>>>(x, th0, thlc, out);
    prep_T<<<dim3(KC, KC), dim3(32, 32)>>>(thlclc);

    quad_tc_kernel<<<320, 256, SMEM_TOTAL>>>(x, out);
}

// round 6
// speedup vs baseline: 5.9326x; 1.7897x over previous
#include <cuda_runtime.h>
#include <cuda_fp16.h>
#include <cstdint>

#define B_DIM 1024
#define C_DIM 20
#define LC    5120
#define KC64  80           // LC / 64 K-chunks
#define TSCALE 256.0f      // theta_lclc scaled by 256 in prep; undone in epilogue

// ---------------------------------------------------------------------------
// Scratch: fp16 pairs, K-major, pair-permuted within each 64-chunk.
// Within a 64-element chunk: k16 sub-chunk c = (k%64)/16, pair p = (k%16)/2,
// stored at word (p&3)*8 + 2*c + (p>>2).  Thread q's fragment words for two
// k16 steps are then ONE uint4 at word q*8 (+4 for steps 2,3).
// ---------------------------------------------------------------------------
__device__ uint32_t g_Xp[(size_t)B_DIM * LC / 2];
__device__ uint32_t g_Tp[(size_t)LC * LC / 2];

__device__ __forceinline__ uint32_t smem_u32(const void* p) {
    uint32_t a;
    asm("{ .reg .u64 t; cvta.to.shared.u64 t, %1; cvt.u32.u64 %0, t; }"
        : "=r"(a) : "l"(p));
    return a;
}
__device__ __forceinline__ void cpa16(uint32_t dst, const char* gbase, uint32_t goff) {
    asm volatile("cp.async.cg.shared.global [%0], [%1], 16;"
                 :: "r"(dst), "l"(__cvta_generic_to_global(gbase + goff)));
}
#define CP_COMMIT() asm volatile("cp.async.commit_group;" ::: "memory")
#define CP_WAIT1()  asm volatile("cp.async.wait_group 1;" ::: "memory")

__device__ __forceinline__ void mma_f16(float c[4],
                                        uint32_t a0, uint32_t a1,
                                        uint32_t a2, uint32_t a3,
                                        uint32_t b0, uint32_t b1) {
    asm("mma.sync.aligned.m16n8k16.row.col.f32.f16.f16.f32 "
        "{%0,%1,%2,%3}, {%4,%5,%6,%7}, {%8,%9}, {%0,%1,%2,%3};"
        : "+f"(c[0]), "+f"(c[1]), "+f"(c[2]), "+f"(c[3])
        : "r"(a0), "r"(a1), "r"(a2), "r"(a3), "r"(b0), "r"(b1));
}

__device__ __forceinline__ int pair_word(int pl /*0..31 pair idx in 64-chunk*/) {
    const int c  = pl >> 3;       // k16 sub-chunk
    const int pc = pl & 7;        // pair within sub-chunk
    return (pc & 3) * 8 + c * 2 + (pc >> 2);
}

// ---------------------------------------------------------------------------
// prep_X: X -> fp16 pairs (permuted) AND out[b] = th0 + <thlc, x_b>
// ---------------------------------------------------------------------------
__global__ void prep_X(const float* __restrict__ X,
                       const float* __restrict__ th0,
                       const float* __restrict__ thlc,
                       float* __restrict__ out) {
    const int b = blockIdx.x;
    const float* xr = X + (size_t)b * LC;
    float s = 0.f;
    for (int k4 = threadIdx.x; k4 < LC / 4; k4 += blockDim.x) {
        const float4 xv = *reinterpret_cast<const float4*>(xr + k4 * 4);
        const float4 tv = *reinterpret_cast<const float4*>(thlc + k4 * 4);
        s += xv.x * tv.x + xv.y * tv.y + xv.z * tv.z + xv.w * tv.w;
        const int k  = k4 * 4;
        const int kc = k >> 6;
        const int pl = (k & 63) >> 1;          // first pair (even)
        uint32_t* base = g_Xp + ((size_t)b * KC64 + kc) * 32;
        __half2 h0 = __floats2half2_rn(xv.x, xv.y);
        __half2 h1 = __floats2half2_rn(xv.z, xv.w);
        base[pair_word(pl)]     = *reinterpret_cast<uint32_t*>(&h0);
        base[pair_word(pl + 1)] = *reinterpret_cast<uint32_t*>(&h1);
    }
    for (int o = 16; o > 0; o >>= 1) s += __shfl_xor_sync(0xffffffffu, s, o);
    __shared__ float red[8];
    if ((threadIdx.x & 31) == 0) red[threadIdx.x >> 5] = s;
    __syncthreads();
    if (threadIdx.x == 0) {
        float t = 0.f;
        #pragma unroll
        for (int w = 0; w < 8; w++) t += red[w];
        out[b] = th0[0] + t;
    }
}

// ---------------------------------------------------------------------------
// prep_T: transpose T (pre-masked), scale by TSCALE, fp16 pairs permuted.
// Tile: 64 i-rows x 32 j-cols. Block (32,32). Writes coalesced (permutation
// stays within one 128B destination row).
// ---------------------------------------------------------------------------
__global__ void prep_T(const float* __restrict__ T) {
    __shared__ float tile[64][33];
    const int i0 = blockIdx.x * 64;
    const int j0 = blockIdx.y * 32;
    const int tx = threadIdx.x, ty = threadIdx.y;
    tile[ty][tx]      = T[(size_t)(i0 + ty)      * LC + j0 + tx];
    tile[ty + 32][tx] = T[(size_t)(i0 + ty + 32) * LC + j0 + tx];
    __syncthreads();
    // thread -> (j = j0+ty, pair pl = tx) ; i = i0 + 2*tx, 2*tx+1
    const float v0 = tile[2 * tx][ty] * TSCALE;
    const float v1 = tile[2 * tx + 1][ty] * TSCALE;
    __half2 h = __floats2half2_rn(v0, v1);
    g_Tp[((size_t)(j0 + ty) * KC64 + (i0 >> 6)) * 32 + pair_word(tx)]
        = *reinterpret_cast<uint32_t*>(&h);
}

// ---------------------------------------------------------------------------
// quad kernel: out[b] += (1/TSCALE) * x_b^T T' x_b
// CTA 128(b) x 128(j) x BK=64 fp16, 256 threads (8 warps: 2m x 4n of 64x32),
// mma.sync m16n8k16 fp16->fp32. 3-stage cp.async pipeline, prefetch dist 2,
// one barrier per chunk. Smem rows 36 words (144B) — conflict-free layout.
// Triangle skip: K to Kmax = floor((j0+127)/C)*C rounded up to 64.
// ---------------------------------------------------------------------------
#define STAGE_BYTES 36864
#define BOFF        18432
#define SMEM_TOTAL  (3 * STAGE_BYTES)

__global__ __launch_bounds__(256, 2)
void quad_tc_kernel(const float* __restrict__ X, float* __restrict__ out) {
    extern __shared__ char smem[];
    const uint32_t sb = smem_u32(smem);
    const int tid  = threadIdx.x;
    const int lane = tid & 31;
    const int w    = tid >> 5;
    const int g    = lane >> 2;
    const int q    = lane & 3;
    const int wm   = w & 1;       // 0..1 : 64 batch rows
    const int wn   = w >> 1;      // 0..3 : 32 j cols

    // work-balanced tile map (heavy->light; co-resident pairs sum ~const)
    const int bid = blockIdx.x;
    int r;
    if (bid < 148)      r = bid * 2;
    else if (bid < 296) r = 591 - 2 * bid;
    else                r = bid;
    const int jt = 39 - (r >> 3);
    const int b0 = (r & 7) << 7;
    const int j0 = jt << 7;

    const int Kmax = ((j0 + 127) / C_DIM) * C_DIM;
    const int KPP  = (Kmax + 63) >> 6;            // 2..80 K-chunks of 64

    // hoisted cp.async source/dst offsets
    const int rowL = tid >> 3;                    // 0..31
    const int ch   = tid & 7;                     // 16B chunk 0..7
    uint32_t gAc[4], gBc[4];
    #pragma unroll
    for (int i = 0; i < 4; i++) {
        const int row = rowL + i * 32;
        gAc[i] = (uint32_t)((b0 + row) * (KC64 * 128) + ch * 16);
        gBc[i] = (uint32_t)((j0 + row) * (KC64 * 128) + ch * 16);
    }
    const uint32_t sAc = (uint32_t)(rowL * 144 + ch * 16);
    const char* gA = (const char*)g_Xp;
    const char* gB = (const char*)g_Tp;

    float acc[4][4][4];
    #pragma unroll
    for (int mt = 0; mt < 4; mt++)
        #pragma unroll
        for (int nt = 0; nt < 4; nt++)
            #pragma unroll
            for (int c = 0; c < 4; c++) acc[mt][nt][c] = 0.f;

    // prologue: prefetch chunks 0,1 (KPP >= 2 always)
    #pragma unroll
    for (int s = 0; s < 2; s++) {
        const uint32_t st = sb + s * STAGE_BYTES + sAc;
        const uint32_t ko = (uint32_t)s * 128;
        #pragma unroll
        for (int i = 0; i < 4; i++) cpa16(st + i * (32 * 144), gA, gAc[i] + ko);
        #pragma unroll
        for (int i = 0; i < 4; i++) cpa16(st + BOFF + i * (32 * 144), gB, gBc[i] + ko);
        CP_COMMIT();
    }

    const uint32_t fA = (uint32_t)((wm * 64 + g) * 144 + q * 32);
    const uint32_t fB = (uint32_t)(BOFF + (wn * 32 + g) * 144 + q * 32);

    int ss = 0;
    for (int ks = 0; ks < KPP; ks++) {
        CP_WAIT1();
        __syncthreads();

        const char* aB = smem + ss * STAGE_BYTES;

        // 4 k16 steps per chunk, processed as 2 step-pairs (sp)
        #pragma unroll
        for (int sp = 0; sp < 2; sp++) {
            uint4 bf[4];
            #pragma unroll
            for (int nt = 0; nt < 4; nt++)
                bf[nt] = *reinterpret_cast<const uint4*>(aB + fB + nt * (8 * 144) + sp * 16);
            #pragma unroll
            for (int mt = 0; mt < 4; mt++) {
                const char* ap = aB + fA + mt * (16 * 144) + sp * 16;
                uint4 al = *reinterpret_cast<const uint4*>(ap);            // row g
                uint4 ah = *reinterpret_cast<const uint4*>(ap + 8 * 144);  // row g+8
                #pragma unroll
                for (int t = 0; t < 2; t++) {   // two k16 steps in this uint4
                    const uint32_t a0 = t ? al.z : al.x;   // (g,   pair q)
                    const uint32_t a2 = t ? al.w : al.y;   // (g,   pair q+4)
                    const uint32_t a1 = t ? ah.z : ah.x;   // (g+8, pair q)
                    const uint32_t a3 = t ? ah.w : ah.y;   // (g+8, pair q+4)
                    #pragma unroll
                    for (int nt = 0; nt < 4; nt++) {
                        const uint32_t b0r = t ? bf[nt].z : bf[nt].x;
                        const uint32_t b1r = t ? bf[nt].w : bf[nt].y;
                        mma_f16(acc[mt][nt], a0, a1, a2, a3, b0r, b1r);
                    }
                }
            }
        }

        // prefetch chunk ks+2 into stage (ss+2)%3 (disjoint from readers)
        if (ks + 2 < KPP) {
            const int s2 = (ss + 2 >= 3) ? ss - 1 : ss + 2;
            const uint32_t st = sb + s2 * STAGE_BYTES + sAc;
            const uint32_t ko = (uint32_t)(ks + 2) * 128;
            #pragma unroll
            for (int i = 0; i < 4; i++) cpa16(st + i * (32 * 144), gA, gAc[i] + ko);
            #pragma unroll
            for (int i = 0; i < 4; i++) cpa16(st + BOFF + i * (32 * 144), gB, gBc[i] + ko);
        }
        CP_COMMIT();

        ss = (ss + 1 >= 3) ? 0 : ss + 1;
    }

    // fused epilogue: out[b] += (1/TSCALE) * sum_j C[b,j] * X[b,j]
    // c0:(g,2q) c1:(g,2q+1) c2:(g+8,2q) c3:(g+8,2q+1)
    #pragma unroll
    for (int mt = 0; mt < 4; mt++) {
        #pragma unroll
        for (int hh = 0; hh < 2; hh++) {
            const int b = b0 + wm * 64 + mt * 16 + g + 8 * hh;
            const float* xr = X + (size_t)b * LC + j0 + wn * 32;
            float s = 0.f;
            #pragma unroll
            for (int nt = 0; nt < 4; nt++) {
                float2 xv = *reinterpret_cast<const float2*>(xr + nt * 8 + 2 * q);
                s += acc[mt][nt][2 * hh] * xv.x + acc[mt][nt][2 * hh + 1] * xv.y;
            }
            s += __shfl_xor_sync(0xffffffffu, s, 1);
            s += __shfl_xor_sync(0xffffffffu, s, 2);
            if (q == 0) atomicAdd(&out[b], s * (1.0f / TSCALE));
        }
    }
}

// ---------------------------------------------------------------------------
// Inputs: x_lc (B,L,C) f32 | theta_0 (1,) | theta_lc (1,L,C) |
//         theta_lclc (1,L,C,L,C) pre-masked f32 | mask (unused)
// Output: (B,1) f32
// ---------------------------------------------------------------------------
extern "C" void kernel_launch(void* const* d_in, const int* in_sizes, int n_in,
                              void* d_out, int out_size) {
    const float* x      = (const float*)d_in[0];
    const float* th0    = (const float*)d_in[1];
    const float* thlc   = (const float*)d_in[2];
    const float* thlclc = (const float*)d_in[3];
    float* out = (float*)d_out;

    cudaFuncSetAttribute(quad_tc_kernel,
                         cudaFuncAttributeMaxDynamicSharedMemorySize, SMEM_TOTAL);

    prep_X<<<B_DIM, 256>>>(x, th0, thlc, out);
    prep_T<<<dim3(LC / 64, LC / 32), dim3(32, 32)>>>(thlclc);

    quad_tc_kernel<<<320, 256, SMEM_TOTAL>>>(x, out);
}

// round 7
// speedup vs baseline: 7.2697x; 1.2254x over previous
#include <cuda_runtime.h>
#include <cuda_fp16.h>
#include <cstdint>

#define B_DIM 1024
#define C_DIM 20
#define LC    5120
#define KC64  80           // LC / 64 K-chunks
#define TSCALE 256.0f      // theta_lclc scaled by 256 in prep; undone in epilogue

// ---------------------------------------------------------------------------
// Scratch: fp16 pairs, K-major, pair-permuted within each 64-chunk.
// Within a 64-element chunk: k16 sub-chunk c = (k%64)/16, pair p = (k%16)/2,
// stored at word (p&3)*8 + 2*c + (p>>2).
// g_Tp is zero-initialized; fully-masked tiles are NEVER written, so they
// remain zero across all graph replays (deterministic).
// ---------------------------------------------------------------------------
__device__ uint32_t g_Xp[(size_t)B_DIM * LC / 2];
__device__ uint32_t g_Tp[(size_t)LC * LC / 2];

__device__ __forceinline__ uint32_t smem_u32(const void* p) {
    uint32_t a;
    asm("{ .reg .u64 t; cvta.to.shared.u64 t, %1; cvt.u32.u64 %0, t; }"
        : "=r"(a) : "l"(p));
    return a;
}
__device__ __forceinline__ void cpa16(uint32_t dst, const char* gbase, uint32_t goff) {
    asm volatile("cp.async.cg.shared.global [%0], [%1], 16;"
                 :: "r"(dst), "l"(__cvta_generic_to_global(gbase + goff)));
}
#define CP_COMMIT() asm volatile("cp.async.commit_group;" ::: "memory")
#define CP_WAIT1()  asm volatile("cp.async.wait_group 1;" ::: "memory")

__device__ __forceinline__ void mma_f16(float c[4],
                                        uint32_t a0, uint32_t a1,
                                        uint32_t a2, uint32_t a3,
                                        uint32_t b0, uint32_t b1) {
    asm("mma.sync.aligned.m16n8k16.row.col.f32.f16.f16.f32 "
        "{%0,%1,%2,%3}, {%4,%5,%6,%7}, {%8,%9}, {%0,%1,%2,%3};"
        : "+f"(c[0]), "+f"(c[1]), "+f"(c[2]), "+f"(c[3])
        : "r"(a0), "r"(a1), "r"(a2), "r"(a3), "r"(b0), "r"(b1));
}

__device__ __forceinline__ int pair_word(int pl) {   // pl = 0..31
    const int c  = pl >> 3;
    const int pc = pl & 7;
    return (pc & 3) * 8 + c * 2 + (pc >> 2);
}

// ---------------------------------------------------------------------------
// prep_X: X -> fp16 pairs (permuted) AND out[b] = th0 + <thlc, x_b>
// ---------------------------------------------------------------------------
__global__ void prep_X(const float* __restrict__ X,
                       const float* __restrict__ th0,
                       const float* __restrict__ thlc,
                       float* __restrict__ out) {
    const int b = blockIdx.x;
    const float* xr = X + (size_t)b * LC;
    float s = 0.f;
    for (int k4 = threadIdx.x; k4 < LC / 4; k4 += blockDim.x) {
        const float4 xv = *reinterpret_cast<const float4*>(xr + k4 * 4);
        const float4 tv = *reinterpret_cast<const float4*>(thlc + k4 * 4);
        s += xv.x * tv.x + xv.y * tv.y + xv.z * tv.z + xv.w * tv.w;
        const int k  = k4 * 4;
        const int kc = k >> 6;
        const int pl = (k & 63) >> 1;
        uint32_t* base = g_Xp + ((size_t)b * KC64 + kc) * 32;
        __half2 h0 = __floats2half2_rn(xv.x, xv.y);
        __half2 h1 = __floats2half2_rn(xv.z, xv.w);
        base[pair_word(pl)]     = *reinterpret_cast<uint32_t*>(&h0);
        base[pair_word(pl + 1)] = *reinterpret_cast<uint32_t*>(&h1);
    }
    for (int o = 16; o > 0; o >>= 1) s += __shfl_xor_sync(0xffffffffu, s, o);
    __shared__ float red[8];
    if ((threadIdx.x & 31) == 0) red[threadIdx.x >> 5] = s;
    __syncthreads();
    if (threadIdx.x == 0) {
        float t = 0.f;
        #pragma unroll
        for (int w = 0; w < 8; w++) t += red[w];
        out[b] = th0[0] + t;
    }
}

// ---------------------------------------------------------------------------
// prep_T: transpose+scale+convert T (pre-masked) into g_Tp, SKIPPING tiles
// that the mask zeroes entirely. 64(i) x 64(j) tile, 256 threads.
// Writes: each thread owns 8 consecutive dest words of one (j, kc) row ->
// warp covers 8 full 128B rows, fully coalesced. Inverse permutation:
//   w -> c=(w&7)>>1, pc=((w&1)<<2)|(w>>3), pl=(c<<3)|pc, i=i0+2*pl(+1)
// ---------------------------------------------------------------------------
__global__ void prep_T(const float* __restrict__ T) {
    const int i0 = blockIdx.x * 64;
    const int j0 = blockIdx.y * 64;
    const int bound = ((j0 + 63) / C_DIM) * C_DIM;   // max nonzero i (excl)
    if (i0 >= bound) return;                          // fully-masked tile

    __shared__ float tile[64][68];
    const int t = threadIdx.x;                        // 0..255

    // load 64x64 f32 (coalesced float4)
    const int lr = t >> 4;            // 0..15
    const int lc = (t & 15) * 4;      // 0..60
    #pragma unroll
    for (int rr = 0; rr < 4; rr++) {
        const int row = lr + rr * 16;
        const float4 v = *reinterpret_cast<const float4*>(
            T + (size_t)(i0 + row) * LC + j0 + lc);
        *reinterpret_cast<float4*>(&tile[row][lc]) = v;
    }
    __syncthreads();

    const int jl = t >> 2;            // 0..63
    const int wb = (t & 3) * 8;       // word base 0,8,16,24
    uint32_t* dst = g_Tp + ((size_t)(j0 + jl) * KC64 + (i0 >> 6)) * 32;
    #pragma unroll
    for (int dw = 0; dw < 8; dw++) {
        const int w  = wb + dw;
        const int c  = (w & 7) >> 1;
        const int pc = ((w & 1) << 2) | (w >> 3);
        const int pl = (c << 3) | pc;
        const float v0 = tile[2 * pl][jl] * TSCALE;
        const float v1 = tile[2 * pl + 1][jl] * TSCALE;
        __half2 h = __floats2half2_rn(v0, v1);
        dst[w] = *reinterpret_cast<uint32_t*>(&h);
    }
}

// ---------------------------------------------------------------------------
// quad kernel: out[b] += (1/TSCALE) * x_b^T T' x_b
// CTA 128(b) x 128(j) x BK=64 fp16, 256 threads (8 warps: 2m x 4n of 64x32),
// mma.sync m16n8k16. 3-stage cp.async pipeline, prefetch dist 2, one
// barrier per chunk. Smem rows 36 words (144B): conflict-free STS + LDS128.
// Triangle skip: K to Kmax = floor((j0+127)/C)*C rounded up to 64.
// ---------------------------------------------------------------------------
#define STAGE_BYTES 36864
#define BOFF        18432
#define SMEM_TOTAL  (3 * STAGE_BYTES)

__global__ __launch_bounds__(256, 2)
void quad_tc_kernel(const float* __restrict__ X, float* __restrict__ out) {
    extern __shared__ char smem[];
    const uint32_t sb = smem_u32(smem);
    const int tid  = threadIdx.x;
    const int lane = tid & 31;
    const int w    = tid >> 5;
    const int g    = lane >> 2;
    const int q    = lane & 3;
    const int wm   = w & 1;
    const int wn   = w >> 1;

    // work-balanced tile map
    const int bid = blockIdx.x;
    int r;
    if (bid < 148)      r = bid * 2;
    else if (bid < 296) r = 591 - 2 * bid;
    else                r = bid;
    const int jt = 39 - (r >> 3);
    const int b0 = (r & 7) << 7;
    const int j0 = jt << 7;

    const int Kmax = ((j0 + 127) / C_DIM) * C_DIM;
    const int KPP  = (Kmax + 63) >> 6;            // 2..80 chunks of 64

    const int rowL = tid >> 3;
    const int ch   = tid & 7;
    uint32_t gAc[4], gBc[4];
    #pragma unroll
    for (int i = 0; i < 4; i++) {
        const int row = rowL + i * 32;
        gAc[i] = (uint32_t)((b0 + row) * (KC64 * 128) + ch * 16);
        gBc[i] = (uint32_t)((j0 + row) * (KC64 * 128) + ch * 16);
    }
    const uint32_t sAc = (uint32_t)(rowL * 144 + ch * 16);
    const char* gA = (const char*)g_Xp;
    const char* gB = (const char*)g_Tp;

    float acc[4][4][4];
    #pragma unroll
    for (int mt = 0; mt < 4; mt++)
        #pragma unroll
        for (int nt = 0; nt < 4; nt++)
            #pragma unroll
            for (int c = 0; c < 4; c++) acc[mt][nt][c] = 0.f;

    #pragma unroll
    for (int s = 0; s < 2; s++) {
        const uint32_t st = sb + s * STAGE_BYTES + sAc;
        const uint32_t ko = (uint32_t)s * 128;
        #pragma unroll
        for (int i = 0; i < 4; i++) cpa16(st + i * (32 * 144), gA, gAc[i] + ko);
        #pragma unroll
        for (int i = 0; i < 4; i++) cpa16(st + BOFF + i * (32 * 144), gB, gBc[i] + ko);
        CP_COMMIT();
    }

    const uint32_t fA = (uint32_t)((wm * 64 + g) * 144 + q * 32);
    const uint32_t fB = (uint32_t)(BOFF + (wn * 32 + g) * 144 + q * 32);

    int ss = 0;
    for (int ks = 0; ks < KPP; ks++) {
        CP_WAIT1();
        __syncthreads();

        const char* aB = smem + ss * STAGE_BYTES;

        #pragma unroll
        for (int sp = 0; sp < 2; sp++) {
            uint4 bf[4];
            #pragma unroll
            for (int nt = 0; nt < 4; nt++)
                bf[nt] = *reinterpret_cast<const uint4*>(aB + fB + nt * (8 * 144) + sp * 16);
            #pragma unroll
            for (int mt = 0; mt < 4; mt++) {
                const char* ap = aB + fA + mt * (16 * 144) + sp * 16;
                uint4 al = *reinterpret_cast<const uint4*>(ap);
                uint4 ah = *reinterpret_cast<const uint4*>(ap + 8 * 144);
                #pragma unroll
                for (int t = 0; t < 2; t++) {
                    const uint32_t a0 = t ? al.z : al.x;
                    const uint32_t a2 = t ? al.w : al.y;
                    const uint32_t a1 = t ? ah.z : ah.x;
                    const uint32_t a3 = t ? ah.w : ah.y;
                    #pragma unroll
                    for (int nt = 0; nt < 4; nt++) {
                        const uint32_t b0r = t ? bf[nt].z : bf[nt].x;
                        const uint32_t b1r = t ? bf[nt].w : bf[nt].y;
                        mma_f16(acc[mt][nt], a0, a1, a2, a3, b0r, b1r);
                    }
                }
            }
        }

        if (ks + 2 < KPP) {
            const int s2 = (ss + 2 >= 3) ? ss - 1 : ss + 2;
            const uint32_t st = sb + s2 * STAGE_BYTES + sAc;
            const uint32_t ko = (uint32_t)(ks + 2) * 128;
            #pragma unroll
            for (int i = 0; i < 4; i++) cpa16(st + i * (32 * 144), gA, gAc[i] + ko);
            #pragma unroll
            for (int i = 0; i < 4; i++) cpa16(st + BOFF + i * (32 * 144), gB, gBc[i] + ko);
        }
        CP_COMMIT();

        ss = (ss + 1 >= 3) ? 0 : ss + 1;
    }

    // fused epilogue: out[b] += (1/TSCALE) * sum_j C[b,j] * X[b,j]
    #pragma unroll
    for (int mt = 0; mt < 4; mt++) {
        #pragma unroll
        for (int hh = 0; hh < 2; hh++) {
            const int b = b0 + wm * 64 + mt * 16 + g + 8 * hh;
            const float* xr = X + (size_t)b * LC + j0 + wn * 32;
            float s = 0.f;
            #pragma unroll
            for (int nt = 0; nt < 4; nt++) {
                float2 xv = *reinterpret_cast<const float2*>(xr + nt * 8 + 2 * q);
                s += acc[mt][nt][2 * hh] * xv.x + acc[mt][nt][2 * hh + 1] * xv.y;
            }
            s += __shfl_xor_sync(0xffffffffu, s, 1);
            s += __shfl_xor_sync(0xffffffffu, s, 2);
            if (q == 0) atomicAdd(&out[b], s * (1.0f / TSCALE));
        }
    }
}

// ---------------------------------------------------------------------------
// Inputs: x_lc (B,L,C) f32 | theta_0 (1,) | theta_lc (1,L,C) |
//         theta_lclc (1,L,C,L,C) pre-masked f32 | mask (unused)
// Output: (B,1) f32
// ---------------------------------------------------------------------------
extern "C" void kernel_launch(void* const* d_in, const int* in_sizes, int n_in,
                              void* d_out, int out_size) {
    const float* x      = (const float*)d_in[0];
    const float* th0    = (const float*)d_in[1];
    const float* thlc   = (const float*)d_in[2];
    const float* thlclc = (const float*)d_in[3];
    float* out = (float*)d_out;

    cudaFuncSetAttribute(quad_tc_kernel,
                         cudaFuncAttributeMaxDynamicSharedMemorySize, SMEM_TOTAL);

    prep_X<<<B_DIM, 256>>>(x, th0, thlc, out);
    prep_T<<<dim3(KC64, LC / 64), 256>>>(thlclc);

    quad_tc_kernel<<<320, 256, SMEM_TOTAL>>>(x, out);
}

// round 9
// speedup vs baseline: 7.6393x; 1.0508x over previous
#include <cuda_runtime.h>
#include <cuda_fp16.h>
#include <cstdint>

#define B_DIM 1024
#define C_DIM 20
#define LC    5120
#define KC64  80           // LC / 64 K-chunks
#define TSCALE 256.0f      // theta_lclc scaled by 256 in prep; undone in epilogue
#define NT_TILES 3200      // prep_T tiles: (LC/64 = 80 i) x (LC/128 = 40 j)

// ---------------------------------------------------------------------------
// Scratch: fp16 pairs, K-major, pair-permuted within each 64-chunk.
// word(pl) for pair pl=0..31:  c=pl>>3, pc=pl&7 -> w = (pc&3)*8 + c*2 + (pc>>2)
// g_Tp is zero-initialized; fully-masked tiles are NEVER written -> stay zero.
// ---------------------------------------------------------------------------
__device__ uint32_t g_Xp[(size_t)B_DIM * LC / 2];
__device__ uint32_t g_Tp[(size_t)LC * LC / 2];

__device__ __forceinline__ uint32_t smem_u32(const void* p) {
    uint32_t a;
    asm("{ .reg .u64 t; cvta.to.shared.u64 t, %1; cvt.u32.u64 %0, t; }"
        : "=r"(a) : "l"(p));
    return a;
}
__device__ __forceinline__ void cpa16(uint32_t dst, const char* gbase, uint32_t goff) {
    asm volatile("cp.async.cg.shared.global [%0], [%1], 16;"
                 :: "r"(dst), "l"(__cvta_generic_to_global(gbase + goff)));
}
#define CP_COMMIT() asm volatile("cp.async.commit_group;" ::: "memory")
#define CP_WAIT1()  asm volatile("cp.async.wait_group 1;" ::: "memory")

__device__ __forceinline__ void mma_f16(float c[4],
                                        uint32_t a0, uint32_t a1,
                                        uint32_t a2, uint32_t a3,
                                        uint32_t b0, uint32_t b1) {
    asm("mma.sync.aligned.m16n8k16.row.col.f32.f16.f16.f32 "
        "{%0,%1,%2,%3}, {%4,%5,%6,%7}, {%8,%9}, {%0,%1,%2,%3};"
        : "+f"(c[0]), "+f"(c[1]), "+f"(c[2]), "+f"(c[3])
        : "r"(a0), "r"(a1), "r"(a2), "r"(a3), "r"(b0), "r"(b1));
}

__device__ __forceinline__ int pair_word(int pl) {
    const int c  = pl >> 3;
    const int pc = pl & 7;
    return (pc & 3) * 8 + c * 2 + (pc >> 2);
}

// ---------------------------------------------------------------------------
// Merged prep kernel.
//   blocks [0, 3200):         prep_T — tile 64(i) x 128(j), triangle-skipped
//   blocks [3200, 3200+1024): prep_X — per-batch convert + init out[b]
// ---------------------------------------------------------------------------
__global__ __launch_bounds__(256)
void prep_all(const float* __restrict__ X,
              const float* __restrict__ th0,
              const float* __restrict__ thlc,
              const float* __restrict__ T,
              float* __restrict__ out) {
    const int blk = blockIdx.x;
    const int t   = threadIdx.x;

    if (blk < NT_TILES) {
        // ----------------- prep_T: transpose+scale+convert -----------------
        const int it = blk % (LC / 64);         // 0..79  (i tile)
        const int jt = blk / (LC / 64);         // 0..39  (j tile of 128)
        const int i0 = it * 64;
        const int j0 = jt * 128;
        const int bound = ((j0 + 127) / C_DIM) * C_DIM;  // max nonzero i (excl)
        if (i0 >= bound) return;                          // fully-masked tile

        __shared__ float tile[64][132];
        // load 64 x 128 f32 (coalesced float4)
        {
            const int row = t >> 2;             // 0..63
            const int c16 = t & 3;
            const float* src = T + (size_t)(i0 + row) * LC + j0;
            #pragma unroll
            for (int rr = 0; rr < 8; rr++) {
                const int col4 = c16 + rr * 4;  // 0..31
                const float4 v = *reinterpret_cast<const float4*>(src + col4 * 4);
                *reinterpret_cast<float4*>(&tile[row][col4 * 4]) = v;
            }
        }
        __syncthreads();

        // write: thread owns (j = j0 + jl, words wb..wb+15) -> 4 x STG.128
        const int jl   = t >> 1;                // 0..127
        const int half = t & 1;
        const int wb   = half * 16;
        uint32_t buf[16];
        #pragma unroll
        for (int dw = 0; dw < 16; dw++) {
            const int w  = wb + dw;
            const int c  = (w & 7) >> 1;
            const int pc = ((w & 1) << 2) | (w >> 3);
            const int pl = (c << 3) | pc;
            const float v0 = tile[2 * pl][jl] * TSCALE;
            const float v1 = tile[2 * pl + 1][jl] * TSCALE;
            __half2 h = __floats2half2_rn(v0, v1);
            buf[dw] = *reinterpret_cast<uint32_t*>(&h);
        }
        uint32_t* dst = g_Tp + ((size_t)(j0 + jl) * KC64 + it) * 32 + wb;
        #pragma unroll
        for (int v = 0; v < 4; v++)
            *reinterpret_cast<uint4*>(dst + v * 4) =
                *reinterpret_cast<const uint4*>(&buf[v * 4]);
    } else {
        // ----------------- prep_X + init out -----------------
        const int b = blk - NT_TILES;
        const float* xr = X + (size_t)b * LC;
        float s = 0.f;
        for (int k4 = t; k4 < LC / 4; k4 += 256) {
            const float4 xv = *reinterpret_cast<const float4*>(xr + k4 * 4);
            const float4 tv = *reinterpret_cast<const float4*>(thlc + k4 * 4);
            s += xv.x * tv.x + xv.y * tv.y + xv.z * tv.z + xv.w * tv.w;
            const int k  = k4 * 4;
            const int kc = k >> 6;
            const int pl = (k & 63) >> 1;
            uint32_t* base = g_Xp + ((size_t)b * KC64 + kc) * 32;
            __half2 h0 = __floats2half2_rn(xv.x, xv.y);
            __half2 h1 = __floats2half2_rn(xv.z, xv.w);
            base[pair_word(pl)]     = *reinterpret_cast<uint32_t*>(&h0);
            base[pair_word(pl + 1)] = *reinterpret_cast<uint32_t*>(&h1);
        }
        for (int o = 16; o > 0; o >>= 1) s += __shfl_xor_sync(0xffffffffu, s, o);
        __shared__ float red[8];
        if ((t & 31) == 0) red[t >> 5] = s;
        __syncthreads();
        if (t == 0) {
            float tt = 0.f;
            #pragma unroll
            for (int w = 0; w < 8; w++) tt += red[w];
            out[b] = th0[0] + tt;
        }
    }
}

// ---------------------------------------------------------------------------
// quad kernel: out[b] += (1/TSCALE) * x_b^T T' x_b   (unchanged — at the
// legacy-HMMA pipe floor)
// ---------------------------------------------------------------------------
#define STAGE_BYTES 36864
#define BOFF        18432
#define SMEM_TOTAL  (3 * STAGE_BYTES)

__global__ __launch_bounds__(256, 2)
void quad_tc_kernel(const float* __restrict__ X, float* __restrict__ out) {
    extern __shared__ char smem[];
    const uint32_t sb = smem_u32(smem);
    const int tid  = threadIdx.x;
    const int lane = tid & 31;
    const int w    = tid >> 5;
    const int g    = lane >> 2;
    const int q    = lane & 3;
    const int wm   = w & 1;
    const int wn   = w >> 1;

    const int bid = blockIdx.x;
    int r;
    if (bid < 148)      r = bid * 2;
    else if (bid < 296) r = 591 - 2 * bid;
    else                r = bid;
    const int jt = 39 - (r >> 3);
    const int b0 = (r & 7) << 7;
    const int j0 = jt << 7;

    const int Kmax = ((j0 + 127) / C_DIM) * C_DIM;
    const int KPP  = (Kmax + 63) >> 6;

    const int rowL = tid >> 3;
    const int ch   = tid & 7;
    uint32_t gAc[4], gBc[4];
    #pragma unroll
    for (int i = 0; i < 4; i++) {
        const int row = rowL + i * 32;
        gAc[i] = (uint32_t)((b0 + row) * (KC64 * 128) + ch * 16);
        gBc[i] = (uint32_t)((j0 + row) * (KC64 * 128) + ch * 16);
    }
    const uint32_t sAc = (uint32_t)(rowL * 144 + ch * 16);
    const char* gA = (const char*)g_Xp;
    const char* gB = (const char*)g_Tp;

    float acc[4][4][4];
    #pragma unroll
    for (int mt = 0; mt < 4; mt++)
        #pragma unroll
        for (int nt = 0; nt < 4; nt++)
            #pragma unroll
            for (int c = 0; c < 4; c++) acc[mt][nt][c] = 0.f;

    #pragma unroll
    for (int s = 0; s < 2; s++) {
        const uint32_t st = sb + s * STAGE_BYTES + sAc;
        const uint32_t ko = (uint32_t)s * 128;
        #pragma unroll
        for (int i = 0; i < 4; i++) cpa16(st + i * (32 * 144), gA, gAc[i] + ko);
        #pragma unroll
        for (int i = 0; i < 4; i++) cpa16(st + BOFF + i * (32 * 144), gB, gBc[i] + ko);
        CP_COMMIT();
    }

    const uint32_t fA = (uint32_t)((wm * 64 + g) * 144 + q * 32);
    const uint32_t fB = (uint32_t)(BOFF + (wn * 32 + g) * 144 + q * 32);

    int ss = 0;
    for (int ks = 0; ks < KPP; ks++) {
        CP_WAIT1();
        __syncthreads();

        const char* aB = smem + ss * STAGE_BYTES;

        #pragma unroll
        for (int sp = 0; sp < 2; sp++) {
            uint4 bf[4];
            #pragma unroll
            for (int nt = 0; nt < 4; nt++)
                bf[nt] = *reinterpret_cast<const uint4*>(aB + fB + nt * (8 * 144) + sp * 16);
            #pragma unroll
            for (int mt = 0; mt < 4; mt++) {
                const char* ap = aB + fA + mt * (16 * 144) + sp * 16;
                uint4 al = *reinterpret_cast<const uint4*>(ap);
                uint4 ah = *reinterpret_cast<const uint4*>(ap + 8 * 144);
                #pragma unroll
                for (int t = 0; t < 2; t++) {
                    const uint32_t a0 = t ? al.z : al.x;
                    const uint32_t a2 = t ? al.w : al.y;
                    const uint32_t a1 = t ? ah.z : ah.x;
                    const uint32_t a3 = t ? ah.w : ah.y;
                    #pragma unroll
                    for (int nt = 0; nt < 4; nt++) {
                        const uint32_t b0r = t ? bf[nt].z : bf[nt].x;
                        const uint32_t b1r = t ? bf[nt].w : bf[nt].y;
                        mma_f16(acc[mt][nt], a0, a1, a2, a3, b0r, b1r);
                    }
                }
            }
        }

        if (ks + 2 < KPP) {
            const int s2 = (ss + 2 >= 3) ? ss - 1 : ss + 2;
            const uint32_t st = sb + s2 * STAGE_BYTES + sAc;
            const uint32_t ko = (uint32_t)(ks + 2) * 128;
            #pragma unroll
            for (int i = 0; i < 4; i++) cpa16(st + i * (32 * 144), gA, gAc[i] + ko);
            #pragma unroll
            for (int i = 0; i < 4; i++) cpa16(st + BOFF + i * (32 * 144), gB, gBc[i] + ko);
        }
        CP_COMMIT();

        ss = (ss + 1 >= 3) ? 0 : ss + 1;
    }

    #pragma unroll
    for (int mt = 0; mt < 4; mt++) {
        #pragma unroll
        for (int hh = 0; hh < 2; hh++) {
            const int b = b0 + wm * 64 + mt * 16 + g + 8 * hh;
            const float* xr = X + (size_t)b * LC + j0 + wn * 32;
            float s = 0.f;
            #pragma unroll
            for (int nt = 0; nt < 4; nt++) {
                float2 xv = *reinterpret_cast<const float2*>(xr + nt * 8 + 2 * q);
                s += acc[mt][nt][2 * hh] * xv.x + acc[mt][nt][2 * hh + 1] * xv.y;
            }
            s += __shfl_xor_sync(0xffffffffu, s, 1);
            s += __shfl_xor_sync(0xffffffffu, s, 2);
            if (q == 0) atomicAdd(&out[b], s * (1.0f / TSCALE));
        }
    }
}

// ---------------------------------------------------------------------------
// Inputs: x_lc (B,L,C) f32 | theta_0 (1,) | theta_lc (1,L,C) |
//         theta_lclc (1,L,C,L,C) pre-masked f32 | mask (unused)
// Output: (B,1) f32
// ---------------------------------------------------------------------------
extern "C" void kernel_launch(void* const* d_in, const int* in_sizes, int n_in,
                              void* d_out, int out_size) {
    const float* x      = (const float*)d_in[0];
    const float* th0    = (const float*)d_in[1];
    const float* thlc   = (const float*)d_in[2];
    const float* thlclc = (const float*)d_in[3];
    float* out = (float*)d_out;

    cudaFuncSetAttribute(quad_tc_kernel,
                         cudaFuncAttributeMaxDynamicSharedMemorySize, SMEM_TOTAL);

    prep_all<<<NT_TILES + B_DIM, 256>>>(x, th0, thlc, thlclc, out);
    quad_tc_kernel<<<320, 256, SMEM_TOTAL>>>(x, out);
}